// round 17
// baseline (speedup 1.0000x reference)
#include <cuda_runtime.h>
#include <cstdint>

#define B_ 32
#define S_ 2048
#define D_ 64
// (1/sqrt(512)) * log2(e): exp(logit) == exp2(mma_result)
#define SCALE2_ (0.044194173824159216f * 1.4426950408889634f)

#define KHST 40  // f16-pair words per Q/K row; LDS.64 conflict-free
#define QHST 40
#define VPST 72  // pair-packed V rows: 64 data words + 8 pad

#define NST 3    // ring stages

// smem byte offsets
#define OFF_QH  0                      // 128*40*4 = 20480
#define OFF_KH  20480                  // 3 stages x 10240
#define KH_SZ   10240
#define OFF_VP  51200                  // 3 stages x 9216
#define VP_SZ   9216
#define OFF_MB  78848                  // 12 mbarriers x 8B
#define SMEM_TOTAL 78976               // ~77.1 KB -> 2 CTAs/SM

__device__ __forceinline__ uint32_t pk2(float lo, float hi) {
    uint32_t r;
    asm("cvt.rn.f16x2.f32 %0, %1, %2;" : "=r"(r) : "f"(hi), "f"(lo));
    return r;
}
__device__ __forceinline__ float pexp2(int m, float x) {
    float r;
    asm("{\n\t.reg .pred p;\n\t"
        "setp.eq.s32 p, %1, 0;\n\t"
        "mov.f32 %0, 0f00000000;\n\t"
        "@p ex2.approx.f32 %0, %2;\n\t}"
        : "=f"(r) : "r"(m), "f"(x));
    return r;
}
__device__ __forceinline__ void mma16(float (&d)[4], uint32_t a0, uint32_t a1,
                                      uint32_t a2, uint32_t a3,
                                      uint32_t b0, uint32_t b1) {
    asm volatile(
        "mma.sync.aligned.m16n8k16.row.col.f32.f16.f16.f32 "
        "{%0,%1,%2,%3}, {%4,%5,%6,%7}, {%8,%9}, {%0,%1,%2,%3};"
        : "+f"(d[0]), "+f"(d[1]), "+f"(d[2]), "+f"(d[3])
        : "r"(a0), "r"(a1), "r"(a2), "r"(a3), "r"(b0), "r"(b1));
}
__device__ __forceinline__ uint32_t smem_u32(const void* p) {
    uint32_t a;
    asm("{ .reg .u64 t; cvta.to.shared.u64 t, %1; cvt.u32.u64 %0, t; }"
        : "=r"(a) : "l"(p));
    return a;
}
// ---- base-PTX mbarrier ----
__device__ __forceinline__ void mb_init(uint32_t a, uint32_t cnt) {
    asm volatile("mbarrier.init.shared.b64 [%0], %1;" :: "r"(a), "r"(cnt) : "memory");
}
__device__ __forceinline__ void mb_arrive(uint32_t a) {
    asm volatile("{ .reg .b64 st; mbarrier.arrive.shared.b64 st, [%0]; }"
                 :: "r"(a) : "memory");
}
__device__ __forceinline__ void mb_wait(uint32_t a, uint32_t ph) {
    uint32_t done;
    do {
        asm volatile(
            "{ .reg .pred p; mbarrier.test_wait.parity.shared.b64 p, [%1], %2; "
            "selp.b32 %0, 1, 0, p; }"
            : "=r"(done) : "r"(a), "r"(ph) : "memory");
        if (!done) __nanosleep(32);
    } while (!done);
}

// =============================================================================
// Fused attention, warp-specialized + RECOMPUTE pass (no attn read-back):
//   Loop A: QK -> exp -> rowsum + PV (no attn store).
//   Loop B: QK recomputed (bit-identical) -> exp*inv -> single attn store.
//   CTA = 320 thr: warps 0-7 consumers, warp 8 K-producer (64 tiles),
//   warp 9 V-producer (32 tiles). grid (16, 32), 2 CTAs/SM.
// =============================================================================
__global__ __launch_bounds__(320, 2) void fused_attn_kernel(
        const float* __restrict__ q, const float* __restrict__ k,
        const float* __restrict__ v, const int* __restrict__ mask,
        float* __restrict__ attn, float* __restrict__ out) {
    extern __shared__ char sm[];
    uint32_t* Qh = (uint32_t*)(sm + OFF_QH);
    const uint32_t smb = smem_u32(sm);

    const int tid = threadIdx.x, lane = tid & 31, wid = tid >> 5;
    const int b = blockIdx.y, i0 = blockIdx.x * 128;

    const float* kg = k + (size_t)b * S_ * D_;
    const float* vg = v + (size_t)b * S_ * D_;

    // mbarrier addresses: fullK[3], emptyK[3], fullV[3], emptyV[3]
    const uint32_t mbFK = smb + OFF_MB;
    const uint32_t mbEK = smb + OFF_MB + 24;
    const uint32_t mbFV = smb + OFF_MB + 48;
    const uint32_t mbEV = smb + OFF_MB + 72;

    if (tid == 0) {
        #pragma unroll
        for (int s = 0; s < NST; s++) {
            mb_init(mbFK + s * 8, 32);
            mb_init(mbEK + s * 8, 256);
            mb_init(mbFV + s * 8, 32);
            mb_init(mbEV + s * 8, 256);
        }
    }

    // ---- stage Q once (consumers' 256 threads): f16 pairs, pi-permuted ----
    if (tid < 256) {
        const float* qg = q + ((size_t)b * S_ + i0) * D_;
        #pragma unroll
        for (int u = 0; u < 2; u++) {
            int idx = tid + u * 256;
            int row = idx >> 2, cg = idx & 3;
            const float* src = qg + row * D_ + cg * 16;
            uint32_t r[8];
            #pragma unroll
            for (int i = 0; i < 4; i++) {
                float4 t = *(const float4*)(src + 4 * i);
                r[2 * i]     = pk2(t.x * SCALE2_, t.y * SCALE2_);
                r[2 * i + 1] = pk2(t.z * SCALE2_, t.w * SCALE2_);
            }
            uint32_t* dst = Qh + row * QHST + cg * 8;
            uint4 w0 = { r[0], r[4], r[1], r[5] };
            uint4 w1 = { r[2], r[6], r[3], r[7] };
            *(uint4*)dst = w0;
            *(uint4*)(dst + 4) = w1;
        }
    }
    __syncthreads();  // publish Q + mbarrier inits; ONLY CTA-wide barrier

    if (wid == 8) {
        // ============ K producer: 64 tiles (two sweeps of 32) ============
        int s = 0, pe = 1;
        #pragma unroll 1
        for (int ct = 0; ct < 64; ++ct) {
            mb_wait(mbEK + s * 8, (uint32_t)pe);
            __threadfence_block();
            uint32_t* Kh = (uint32_t*)(sm + OFF_KH + s * KH_SZ);
            const float* kt = kg + (size_t)((ct & 31) * 64) * D_;
            #pragma unroll 4
            for (int t = 0; t < 32; t++) {
                int ff = t * 32 + lane;
                int row = ff >> 4, i4 = ff & 15;
                int cg = i4 >> 2, i = i4 & 3;
                float4 tv = __ldg((const float4*)(kt + row * D_ + i4 * 4));
                uint32_t w0 = pk2(tv.x, tv.y);
                uint32_t w1 = pk2(tv.z, tv.w);
                int pos0 = (i < 2) ? (cg * 8 + 4 * i) : (cg * 8 + 4 * (i - 2) + 1);
                Kh[row * KHST + pos0]     = w0;
                Kh[row * KHST + pos0 + 2] = w1;
            }
            __threadfence_block();
            mb_arrive(mbFK + s * 8);
            if (++s == NST) { s = 0; pe ^= 1; }
        }
    } else if (wid == 9) {
        // ============ V producer: 32 tiles (loop A only) ============
        int s = 0, pe = 1;
        #pragma unroll 1
        for (int ct = 0; ct < 32; ++ct) {
            mb_wait(mbEV + s * 8, (uint32_t)pe);
            __threadfence_block();
            uint32_t* Vp = (uint32_t*)(sm + OFF_VP + s * VP_SZ);
            const float* vt = vg + (size_t)(ct * 64) * D_;
            #pragma unroll 4
            for (int t = 0; t < 16; t++) {
                int ff = t * 32 + lane;
                int jp = ff >> 4, q4 = ff & 15;
                const float* s0 = vt + (2 * jp) * D_ + q4 * 4;
                float4 a = __ldg((const float4*)s0);
                float4 c = __ldg((const float4*)(s0 + D_));
                uint4 w = { pk2(a.x, c.x), pk2(a.y, c.y),
                            pk2(a.z, c.z), pk2(a.w, c.w) };
                *(uint4*)(Vp + jp * VPST + q4 * 4) = w;
            }
            __threadfence_block();
            mb_arrive(mbFV + s * 8);
            if (++s == NST) { s = 0; pe ^= 1; }
        }
    } else {
        // ================== consumers (warps 0-7) ==================
        const int wm = wid * 16;
        const int g = lane >> 2, e = lane & 3;
        const size_t rowg  = ((size_t)b * S_ + i0 + wm + g) * S_;
        const size_t rowg8 = rowg + 8 * (size_t)S_;

        // hoisted Q fragments (cheap; Q published)
        uint2 qfa[4], qfb[4];
        #pragma unroll
        for (int ks = 0; ks < 4; ++ks) {
            qfa[ks] = *(const uint2*)(Qh + (wm + g) * QHST + ks * 8 + 2 * e);
            qfb[ks] = *(const uint2*)(Qh + (wm + 8 + g) * QHST + ks * 8 + 2 * e);
        }

        float accpv[8][4];
        #pragma unroll
        for (int dj = 0; dj < 8; dj++)
            #pragma unroll
            for (int c = 0; c < 4; c++) accpv[dj][c] = 0.f;
        float rsum0 = 0.f, rsum1 = 0.f;

        int sk = 0, phk = 0, sv = 0, phv = 0;

        // =========== LOOP A: rowsum + PV (no attn store) ===========
        #pragma unroll 1
        for (int ct = 0; ct < 32; ++ct) {
            const int j0 = ct * 64;
            uint32_t* Kh = (uint32_t*)(sm + OFF_KH + sk * KH_SZ);

            mb_wait(mbFK + sk * 8, (uint32_t)phk);
            __threadfence_block();

            float accq[8][4];
            #pragma unroll
            for (int nj = 0; nj < 8; nj++)
                #pragma unroll
                for (int c = 0; c < 4; c++) accq[nj][c] = 0.f;
            #pragma unroll
            for (int ks = 0; ks < 4; ++ks) {
                #pragma unroll
                for (int nj = 0; nj < 8; nj++) {
                    uint2 kb = *(const uint2*)(Kh + (nj * 8 + g) * KHST + ks * 8 + 2 * e);
                    mma16(accq[nj], qfa[ks].x, qfb[ks].x, qfa[ks].y, qfb[ks].y,
                          kb.x, kb.y);
                }
            }
            mb_arrive(mbEK + sk * 8);           // K stage released early
            if (++sk == NST) { sk = 0; phk ^= 1; }

            // mask -> exp2 -> rowsum + in-register P
            float sg = 0.f, sg8 = 0.f;
            #pragma unroll
            for (int nj = 0; nj < 8; nj++) {
                int co = j0 + nj * 8 + 2 * e;
                int2 mg = *(const int2*)(mask + rowg + co);
                int2 mh = *(const int2*)(mask + rowg8 + co);
                float e0 = pexp2(mg.x, accq[nj][0]);
                float e1 = pexp2(mg.y, accq[nj][1]);
                float e2 = pexp2(mh.x, accq[nj][2]);
                float e3 = pexp2(mh.y, accq[nj][3]);
                sg += e0 + e1;
                sg8 += e2 + e3;
                accq[nj][0] = e0; accq[nj][1] = e1;
                accq[nj][2] = e2; accq[nj][3] = e3;
            }
            sg  += __shfl_xor_sync(0xffffffffu, sg, 1);
            sg  += __shfl_xor_sync(0xffffffffu, sg, 2);
            sg8 += __shfl_xor_sync(0xffffffffu, sg8, 1);
            sg8 += __shfl_xor_sync(0xffffffffu, sg8, 2);
            rsum0 += sg;
            rsum1 += sg8;

            uint32_t* Vp = (uint32_t*)(sm + OFF_VP + sv * VP_SZ);
            mb_wait(mbFV + sv * 8, (uint32_t)phv);
            __threadfence_block();

            #pragma unroll
            for (int ksj = 0; ksj < 4; ++ksj) {
                uint32_t a0 = pk2(accq[2 * ksj][0], accq[2 * ksj][1]);
                uint32_t a1 = pk2(accq[2 * ksj][2], accq[2 * ksj][3]);
                uint32_t a2 = pk2(accq[2 * ksj + 1][0], accq[2 * ksj + 1][1]);
                uint32_t a3 = pk2(accq[2 * ksj + 1][2], accq[2 * ksj + 1][3]);
                const uint32_t* vr0 = Vp + (8 * ksj + e) * VPST;
                const uint32_t* vr1 = Vp + (8 * ksj + e + 4) * VPST;
                #pragma unroll
                for (int dj = 0; dj < 8; dj++) {
                    uint32_t b0 = vr0[dj * 8 + g];
                    uint32_t b1 = vr1[dj * 8 + g];
                    mma16(accpv[dj], a0, a1, a2, a3, b0, b1);
                }
            }
            mb_arrive(mbEV + sv * 8);
            if (++sv == NST) { sv = 0; phv ^= 1; }
        }

        // ---- inv + out write ----
        const float inv0 = __frcp_rn(rsum0);
        const float inv1 = __frcp_rn(rsum1);
        {
            float* o0 = out + ((size_t)b * S_ + i0 + wm + g) * D_;
            float* o1 = out + ((size_t)b * S_ + i0 + wm + 8 + g) * D_;
            #pragma unroll
            for (int dj = 0; dj < 8; dj++) {
                float2 w0 = { accpv[dj][0] * inv0, accpv[dj][1] * inv0 };
                float2 w1 = { accpv[dj][2] * inv1, accpv[dj][3] * inv1 };
                *(float2*)(o0 + dj * 8 + 2 * e) = w0;
                *(float2*)(o1 + dj * 8 + 2 * e) = w1;
            }
        }

        // ====== LOOP B: recompute QK -> exp*inv -> normalized attn store ======
        #pragma unroll 1
        for (int ct = 0; ct < 32; ++ct) {
            const int j0 = ct * 64;
            uint32_t* Kh = (uint32_t*)(sm + OFF_KH + sk * KH_SZ);

            mb_wait(mbFK + sk * 8, (uint32_t)phk);
            __threadfence_block();

            float accq[8][4];
            #pragma unroll
            for (int nj = 0; nj < 8; nj++)
                #pragma unroll
                for (int c = 0; c < 4; c++) accq[nj][c] = 0.f;
            #pragma unroll
            for (int ks = 0; ks < 4; ++ks) {
                #pragma unroll
                for (int nj = 0; nj < 8; nj++) {
                    uint2 kb = *(const uint2*)(Kh + (nj * 8 + g) * KHST + ks * 8 + 2 * e);
                    mma16(accq[nj], qfa[ks].x, qfb[ks].x, qfa[ks].y, qfb[ks].y,
                          kb.x, kb.y);
                }
            }
            mb_arrive(mbEK + sk * 8);
            if (++sk == NST) { sk = 0; phk ^= 1; }

            #pragma unroll
            for (int nj = 0; nj < 8; nj++) {
                int co = j0 + nj * 8 + 2 * e;
                int2 mg = *(const int2*)(mask + rowg + co);
                int2 mh = *(const int2*)(mask + rowg8 + co);
                float2 w0 = { pexp2(mg.x, accq[nj][0]) * inv0,
                              pexp2(mg.y, accq[nj][1]) * inv0 };
                float2 w1 = { pexp2(mh.x, accq[nj][2]) * inv1,
                              pexp2(mh.y, accq[nj][3]) * inv1 };
                *(float2*)(attn + rowg + co) = w0;
                *(float2*)(attn + rowg8 + co) = w1;
            }
        }
    }
}

// =============================================================================
extern "C" void kernel_launch(void* const* d_in, const int* in_sizes, int n_in,
                              void* d_out, int out_size) {
    const float* q = (const float*)d_in[0];
    const float* k = (const float*)d_in[1];
    const float* v = (const float*)d_in[2];
    const int* mask = (const int*)d_in[3];

    float* out  = (float*)d_out;                 // [B,S,D]
    float* attn = out + (size_t)B_ * S_ * D_;    // [B,S,S]

    cudaFuncSetAttribute(fused_attn_kernel,
                         cudaFuncAttributeMaxDynamicSharedMemorySize, SMEM_TOTAL);

    dim3 grid(S_ / 128, B_);
    fused_attn_kernel<<<grid, 320, SMEM_TOTAL>>>(q, k, v, mask, attn, out);
}